// round 14
// baseline (speedup 1.0000x reference)
#include <cuda_runtime.h>
#include <cuda_bf16.h>
#include <cstdint>

#define BB 16
#define NN 128
#define HD 128
#define ED 64
#define MD 128
#define SLOTS 72
#define SJ 68
#define SM2 132

typedef unsigned long long u64;
typedef unsigned int u32;

// Scratch: c1[b,j,m] = h[b,j]@W1 + bias ; c2[b,i,m] = h[b,i]@W2
__device__ float g_c1[BB * NN * MD];
__device__ float g_c2[BB * NN * MD];

// ---------------- smem offsets (bytes), message kernel ----------------
#define ADJ_OFF 0                         // float[2][128]
#define ACTJ_OFF 1024                     // int[2][SLOTS]
#define NACT_OFF 1600                     // int[2]
#define E_OFF 1664                        // float[2][SLOTS*SJ]
#define EBUF (SLOTS * SJ)                 // 4896 floats per buffer
#define STG_OFF (E_OFF + 2 * EBUF * 4)    // 40832
#define STGF (32 * SM2)                   // 4224 floats per stage buffer
#define SMEM_BYTES (STG_OFF + 2 * STGF * 4)  // 74624  (x3 = 223.9KB/SM)

__device__ __forceinline__ u32 f2tf32(float x) {
    u32 r;
    asm("cvt.rna.tf32.f32 %0, %1;" : "=r"(r) : "f"(x));
    return r;
}
__device__ __forceinline__ void mma_tf32(float c[4], const u32 a[4], u32 b0, u32 b1) {
    asm volatile(
        "mma.sync.aligned.m16n8k8.row.col.f32.tf32.tf32.f32 "
        "{%0,%1,%2,%3}, {%4,%5,%6,%7}, {%8,%9}, {%0,%1,%2,%3};"
        : "+f"(c[0]), "+f"(c[1]), "+f"(c[2]), "+f"(c[3])
        : "r"(a[0]), "r"(a[1]), "r"(a[2]), "r"(a[3]), "r"(b0), "r"(b1));
}
__device__ __forceinline__ u32 smem_u32(const void* p) {
    u32 a;
    asm("{ .reg .u64 t; cvta.to.shared.u64 t, %1; cvt.u32.u64 %0, t; }"
        : "=r"(a) : "l"(p));
    return a;
}
__device__ __forceinline__ void cp16(u32 dst, const void* src) {
    asm volatile("cp.async.cg.shared.global [%0], [%1], 16;"
                 :: "r"(dst), "l"(src) : "memory");
}
#define CP_COMMIT() asm volatile("cp.async.commit_group;" ::: "memory")
#define CP_WAIT1()  asm volatile("cp.async.wait_group 1;" ::: "memory")

// ---------------- Kernel 1: tf32 hi/lo tensor-core precompute ----------------
// 128 blocks x 256 threads. Block = 16 h-rows x 256 combined outputs
// (warps 0-3: c1 = h@W1 + bias; warps 4-7: c2 = h@W2).
// fp32 accuracy via 3-pass hi/lo: hi = bits & 0xFFFFE000 (exact),
// lo = rna_tf32(v - hi). D = Ahi*Bhi + Ahi*Blo + Alo*Bhi (lo*lo ~ 2^-26 dropped).
__global__ __launch_bounds__(256) void precompute_kernel(
    const float* __restrict__ h, const float* __restrict__ W,
    const float* __restrict__ bias) {
    __shared__ u32 hs_hi[16 * 132];
    __shared__ u32 hs_lo[16 * 132];
    const int t = threadIdx.x;
    const int warp = t >> 5, lane = t & 31;
    const int g = lane >> 2, tg = lane & 3;
    const int rb = blockIdx.x * 16;

    for (int f = t; f < 16 * HD; f += 256) {
        const int r = f >> 7, k = f & 127;
        const float v = h[(size_t)(rb + r) * HD + k];
        const u32 hb = __float_as_uint(v) & 0xFFFFE000u;
        hs_hi[r * 132 + k] = hb;
        hs_lo[r * 132 + k] = f2tf32(v - __uint_as_float(hb));
    }
    __syncthreads();

    const bool is1 = warp < 4;
    const int cc = (warp & 3) * 32;
    const float* __restrict__ Wb = W + (size_t)(is1 ? 0 : HD) * MD;

    float acc[4][4];
#pragma unroll
    for (int nt = 0; nt < 4; nt++)
#pragma unroll
        for (int r = 0; r < 4; r++) acc[nt][r] = 0.f;

#pragma unroll 2
    for (int kc = 0; kc < 16; kc++) {
        u32 ah[4], al[4];
        ah[0] = hs_hi[g * 132 + kc * 8 + tg];
        ah[1] = hs_hi[(g + 8) * 132 + kc * 8 + tg];
        ah[2] = hs_hi[g * 132 + kc * 8 + tg + 4];
        ah[3] = hs_hi[(g + 8) * 132 + kc * 8 + tg + 4];
        al[0] = hs_lo[g * 132 + kc * 8 + tg];
        al[1] = hs_lo[(g + 8) * 132 + kc * 8 + tg];
        al[2] = hs_lo[g * 132 + kc * 8 + tg + 4];
        al[3] = hs_lo[(g + 8) * 132 + kc * 8 + tg + 4];
        const float* wk0 = &Wb[(size_t)(kc * 8 + tg) * MD + cc + g];
        const float* wk1 = &Wb[(size_t)(kc * 8 + tg + 4) * MD + cc + g];
#pragma unroll
        for (int nt = 0; nt < 4; nt++) {
            const float w0 = __ldg(&wk0[nt * 8]);
            const float w1 = __ldg(&wk1[nt * 8]);
            const u32 b0h = __float_as_uint(w0) & 0xFFFFE000u;
            const u32 b1h = __float_as_uint(w1) & 0xFFFFE000u;
            const u32 b0l = f2tf32(w0 - __uint_as_float(b0h));
            const u32 b1l = f2tf32(w1 - __uint_as_float(b1h));
            mma_tf32(acc[nt], ah, b0h, b1h);
            mma_tf32(acc[nt], ah, b0l, b1l);
            mma_tf32(acc[nt], al, b0h, b1h);
        }
    }

    // D layout: d0=D[g][2tg], d1=D[g][2tg+1], d2=D[g+8][2tg], d3=D[g+8][2tg+1]
    if (is1) {
#pragma unroll
        for (int nt = 0; nt < 4; nt++) {
            const int col = cc + nt * 8 + 2 * tg;
            const float2 bv = *reinterpret_cast<const float2*>(&bias[col]);
            *reinterpret_cast<float2*>(&g_c1[(size_t)(rb + g) * MD + col]) =
                make_float2(acc[nt][0] + bv.x, acc[nt][1] + bv.y);
            *reinterpret_cast<float2*>(&g_c1[(size_t)(rb + g + 8) * MD + col]) =
                make_float2(acc[nt][2] + bv.x, acc[nt][3] + bv.y);
        }
    } else {
#pragma unroll
        for (int nt = 0; nt < 4; nt++) {
            const int col = cc + nt * 8 + 2 * tg;
            *reinterpret_cast<float2*>(&g_c2[(size_t)(rb + g) * MD + col]) =
                make_float2(acc[nt][0], acc[nt][1]);
            *reinterpret_cast<float2*>(&g_c2[(size_t)(rb + g + 8) * MD + col]) =
                make_float2(acc[nt][2], acc[nt][3]);
        }
    }
}

// ---------------- Kernel 2: persistent sparse tf32 message kernel ----------------
// R8 structure; compaction now ballot-based (1 atomic per warp instead of
// 1 per active lane -> removes ~400 cyc ATOMS serialization per tile).
__global__ __launch_bounds__(256, 3) void message_kernel(
    const float* __restrict__ e, const float* __restrict__ adj,
    const float* __restrict__ W, float* __restrict__ out) {
    extern __shared__ char smc[];
    const u32 smb = smem_u32(smc);
    float* adjA = reinterpret_cast<float*>(smc + ADJ_OFF);
    int* actj = reinterpret_cast<int*>(smc + ACTJ_OFF);
    int* nact = reinterpret_cast<int*>(smc + NACT_OFF);
    u32* e_su = reinterpret_cast<u32*>(smc + E_OFF);
    float* stg = reinterpret_cast<float*>(smc + STG_OFF);

    const int t = threadIdx.x;
    const int warp = t >> 5, lane = t & 31;
    const int g = lane >> 2, tg = lane & 3;
    const int mw = warp * 16;

    if (t < 2) nact[t] = 0;

    // W3^T A-fragments (tf32, rna): warp owns m in [16w, 16w+16).
    u32 afr[8][4];
    {
        const int col = mw + g;
#pragma unroll
        for (int kc = 0; kc < 8; kc++) {
            const int k0 = 2 * HD + kc * 8;
            afr[kc][0] = f2tf32(W[(size_t)(k0 + tg) * MD + col]);
            afr[kc][1] = f2tf32(W[(size_t)(k0 + tg) * MD + col + 8]);
            afr[kc][2] = f2tf32(W[(size_t)(k0 + tg + 4) * MD + col]);
            afr[kc][3] = f2tf32(W[(size_t)(k0 + tg + 4) * MD + col + 8]);
        }
    }
    __syncthreads();

    // Ballot compaction helper (t < NN only; warps 0-3 fully active).
    auto compact = [&](int tile, int buf) {
        const float a = __ldg(&adj[(size_t)tile * NN + t]);
        adjA[buf * NN + t] = a;
        const u32 mask = __ballot_sync(0xFFFFFFFFu, a != 0.f);
        int base = 0;
        if (lane == 0 && mask) base = atomicAdd(&nact[buf], (int)__popc(mask));
        base = __shfl_sync(0xFFFFFFFFu, base, 0);
        if (a != 0.f) {
            const int s = base + (int)__popc(mask & ((1u << lane) - 1u));
            if (s < SLOTS) actj[buf * SLOTS + s] = t;
        }
    };

    // Prologue: compact + prefetch the first tile into buffer 0.
    int cur = blockIdx.x;
    if (cur < BB * NN) {
        if (t < NN) compact(cur, 0);
        __syncthreads();
        const int na0 = min(nact[0], SLOTS);
        for (int f = t; f < na0 * 16; f += 256) {
            const int s = f >> 4, j = actj[s];
            cp16(smb + E_OFF + (u32)(s * SJ + (f & 15) * 4) * 4,
                 e + ((size_t)cur * NN + j) * ED + (f & 15) * 4);
        }
    }
    CP_COMMIT();

    int cbuf = 0;
    for (; cur < BB * NN; cur += gridDim.x) {
        const int nb = 1 - cbuf;
        const int nxt = cur + gridDim.x;

        // Compaction for NEXT tile (buffer nb).
        if (nxt < BB * NN && t < NN) compact(nxt, nb);

        // Zero-fill inactive rows of CUR (overlaps with compaction latency).
        float* __restrict__ orow = out + (size_t)cur * NN * MD;
        {
            const float4 z = make_float4(0.f, 0.f, 0.f, 0.f);
#pragma unroll
            for (int i2 = 0; i2 < 16; i2++) {
                const int idx = t + i2 * 256;
                const int j = idx >> 5, q = idx & 31;
                if (adjA[cbuf * NN + j] == 0.f)
                    __stcs(reinterpret_cast<float4*>(&orow[(size_t)j * MD + q * 4]), z);
            }
        }
        __syncthreads();  // compaction of nxt visible

        // Issue cp.asyncs for NEXT tile's active rows.
        if (nxt < BB * NN) {
            const int na2 = min(nact[nb], SLOTS);
            for (int f = t; f < na2 * 16; f += 256) {
                const int s = f >> 4, j = actj[nb * SLOTS + s];
                cp16(smb + E_OFF + (u32)(nb * EBUF + s * SJ + (f & 15) * 4) * 4,
                     e + ((size_t)nxt * NN + j) * ED + (f & 15) * 4);
            }
        }
        CP_COMMIT();
        CP_WAIT1();       // CUR's e data landed (NEXT's group still in flight)
        __syncthreads();  // visible block-wide

        const int na = min(nact[cbuf], SLOTS);
        const float4 c2r = __ldg(reinterpret_cast<const float4*>(
            &g_c2[(size_t)cur * MD + 4 * lane]));
        const float* __restrict__ c1b = g_c1 + (size_t)(cur >> 7) * NN * MD;
        const u32* __restrict__ ebase = e_su + cbuf * EBUF;
        const int nbatch = (na + 31) >> 5;

        for (int sb = 0; sb < nbatch; sb++) {
            float* buf = stg + (sb & 1) * STGF;
#pragma unroll
            for (int q = 0; q < 4; q++) {
                const int sl = sb * 32 + q * 8 + g;
                float a0[4] = {0.f, 0.f, 0.f, 0.f};
                const u32* br = &ebase[sl * SJ + tg];
#pragma unroll
                for (int kc = 0; kc < 8; kc++)
                    mma_tf32(a0, afr[kc], br[kc * 8], br[kc * 8 + 4]);
                const int r0 = (q * 8 + 2 * tg) * SM2 + mw + g;
                buf[r0] = a0[0];
                buf[r0 + SM2] = a0[1];
                buf[r0 + 8] = a0[2];
                buf[r0 + SM2 + 8] = a0[3];
            }
            if (sb > 0) {
                const int pb = sb - 1;
                const float* pbuf = stg + (pb & 1) * STGF;
#pragma unroll
                for (int i2 = 0; i2 < 4; i2++) {
                    const int r = i2 * 8 + warp;
                    const int slot = pb * 32 + r;
                    if (slot < na) {
                        const int j = actj[cbuf * SLOTS + slot];
                        const float4 d = *reinterpret_cast<const float4*>(
                            &pbuf[r * SM2 + 4 * lane]);
                        const float4 c1 = __ldg(reinterpret_cast<const float4*>(
                            &c1b[(size_t)j * MD + 4 * lane]));
                        __stcs(reinterpret_cast<float4*>(&orow[(size_t)j * MD + 4 * lane]),
                               make_float4(d.x + c1.x + c2r.x, d.y + c1.y + c2r.y,
                                           d.z + c1.z + c2r.z, d.w + c1.w + c2r.w));
                    }
                }
            }
            __syncthreads();
        }
        if (nbatch > 0) {
            const int pb = nbatch - 1;
            const float* pbuf = stg + (pb & 1) * STGF;
#pragma unroll
            for (int i2 = 0; i2 < 4; i2++) {
                const int r = i2 * 8 + warp;
                const int slot = pb * 32 + r;
                if (slot < na) {
                    const int j = actj[cbuf * SLOTS + slot];
                    const float4 d = *reinterpret_cast<const float4*>(
                        &pbuf[r * SM2 + 4 * lane]);
                    const float4 c1 = __ldg(reinterpret_cast<const float4*>(
                        &c1b[(size_t)j * MD + 4 * lane]));
                    __stcs(reinterpret_cast<float4*>(&orow[(size_t)j * MD + 4 * lane]),
                           make_float4(d.x + c1.x + c2r.x, d.y + c1.y + c2r.y,
                                       d.z + c1.z + c2r.z, d.w + c1.w + c2r.w));
                }
            }
        }
        if (t == 0) nact[cbuf] = 0;
        cbuf = nb;
        __syncthreads();  // epi/actj reuse + nact reset ordered before next compaction
    }
}

extern "C" void kernel_launch(void* const* d_in, const int* in_sizes, int n_in,
                              void* d_out, int out_size) {
    const float* h    = (const float*)d_in[0];
    const float* e    = (const float*)d_in[1];
    const float* adj  = (const float*)d_in[2];
    const float* W    = (const float*)d_in[3];
    const float* bias = (const float*)d_in[4];
    float* out = (float*)d_out;

    cudaFuncSetAttribute(message_kernel,
                         cudaFuncAttributeMaxDynamicSharedMemorySize, SMEM_BYTES);

    precompute_kernel<<<128, 256>>>(h, W, bias);
    message_kernel<<<444, 256, SMEM_BYTES>>>(e, adj, W, out);
}

// round 15
// speedup vs baseline: 1.0830x; 1.0830x over previous
#include <cuda_runtime.h>
#include <cuda_bf16.h>
#include <cstdint>

#define BB 16
#define NN 128
#define HD 128
#define ED 64
#define MD 128
#define SLOTS 72
#define SJ 68
#define SM2 132

typedef unsigned long long u64;
typedef unsigned int u32;

// Scratch: c1[b,j,m] = h[b,j]@W1 + bias ; c2[b,i,m] = h[b,i]@W2
__device__ float g_c1[BB * NN * MD];
__device__ float g_c2[BB * NN * MD];

// ---------------- smem offsets (bytes), message kernel ----------------
#define ADJ_OFF 0                         // float[2][128]
#define ACTJ_OFF 1024                     // int[2][SLOTS]
#define NACT_OFF 1600                     // int[2]
#define E_OFF 1664                        // float[2][SLOTS*SJ]
#define EBUF (SLOTS * SJ)                 // 4896 floats per buffer
#define STG_OFF (E_OFF + 2 * EBUF * 4)    // 40832
#define STGF (32 * SM2)                   // 4224 floats per stage buffer
#define SMEM_BYTES (STG_OFF + 2 * STGF * 4)  // 74624  (x3 = 223.9KB/SM)

__device__ __forceinline__ u32 f2tf32(float x) {
    u32 r;
    asm("cvt.rna.tf32.f32 %0, %1;" : "=r"(r) : "f"(x));
    return r;
}
__device__ __forceinline__ void mma_tf32(float c[4], const u32 a[4], u32 b0, u32 b1) {
    asm volatile(
        "mma.sync.aligned.m16n8k8.row.col.f32.tf32.tf32.f32 "
        "{%0,%1,%2,%3}, {%4,%5,%6,%7}, {%8,%9}, {%0,%1,%2,%3};"
        : "+f"(c[0]), "+f"(c[1]), "+f"(c[2]), "+f"(c[3])
        : "r"(a[0]), "r"(a[1]), "r"(a[2]), "r"(a[3]), "r"(b0), "r"(b1));
}
__device__ __forceinline__ u32 smem_u32(const void* p) {
    u32 a;
    asm("{ .reg .u64 t; cvta.to.shared.u64 t, %1; cvt.u32.u64 %0, t; }"
        : "=r"(a) : "l"(p));
    return a;
}
__device__ __forceinline__ void cp16(u32 dst, const void* src) {
    asm volatile("cp.async.cg.shared.global [%0], [%1], 16;"
                 :: "r"(dst), "l"(src) : "memory");
}
#define CP_COMMIT() asm volatile("cp.async.commit_group;" ::: "memory")
#define CP_WAIT1()  asm volatile("cp.async.wait_group 1;" ::: "memory")

// ---------------- Kernel 1: precompute c1, c2 (R8 scalar, 512 blocks) ----------------
__global__ __launch_bounds__(128) void precompute_kernel(
    const float* __restrict__ h, const float* __restrict__ W,
    const float* __restrict__ bias) {
    __shared__ float h_s[4 * 128];
    const int t = threadIdx.x;
    const int rb = blockIdx.x * 4;

#pragma unroll
    for (int q = 0; q < 4; q++)
        h_s[q * 128 + t] = h[(size_t)(rb + q) * HD + t];
    __syncthreads();

    float acc1[4], acc2[4];
#pragma unroll
    for (int r = 0; r < 4; r++) { acc1[r] = 0.f; acc2[r] = 0.f; }

#pragma unroll 4
    for (int k = 0; k < HD; k++) {
        const float w1 = W[(size_t)k * MD + t];
        const float w2 = W[(size_t)(HD + k) * MD + t];
#pragma unroll
        for (int r = 0; r < 4; r++) {
            const float hv = h_s[r * 128 + k];
            acc1[r] = fmaf(hv, w1, acc1[r]);
            acc2[r] = fmaf(hv, w2, acc2[r]);
        }
    }

    const float bv = bias[t];
#pragma unroll
    for (int r = 0; r < 4; r++) {
        g_c1[(size_t)(rb + r) * MD + t] = acc1[r] + bv;
        g_c2[(size_t)(rb + r) * MD + t] = acc2[r];
    }
}

// ---------------- Kernel 2: persistent sparse tf32 message kernel ----------------
// R8 structure + ballot compaction (R14) + ragged last batch (qmax bound):
// the final slot-batch only runs the q-chunks that contain live slots.
__global__ __launch_bounds__(256, 3) void message_kernel(
    const float* __restrict__ e, const float* __restrict__ adj,
    const float* __restrict__ W, float* __restrict__ out) {
    extern __shared__ char smc[];
    const u32 smb = smem_u32(smc);
    float* adjA = reinterpret_cast<float*>(smc + ADJ_OFF);
    int* actj = reinterpret_cast<int*>(smc + ACTJ_OFF);
    int* nact = reinterpret_cast<int*>(smc + NACT_OFF);
    u32* e_su = reinterpret_cast<u32*>(smc + E_OFF);
    float* stg = reinterpret_cast<float*>(smc + STG_OFF);

    const int t = threadIdx.x;
    const int warp = t >> 5, lane = t & 31;
    const int g = lane >> 2, tg = lane & 3;
    const int mw = warp * 16;

    if (t < 2) nact[t] = 0;

    // W3^T A-fragments (tf32, rna): warp owns m in [16w, 16w+16).
    u32 afr[8][4];
    {
        const int col = mw + g;
#pragma unroll
        for (int kc = 0; kc < 8; kc++) {
            const int k0 = 2 * HD + kc * 8;
            afr[kc][0] = f2tf32(W[(size_t)(k0 + tg) * MD + col]);
            afr[kc][1] = f2tf32(W[(size_t)(k0 + tg) * MD + col + 8]);
            afr[kc][2] = f2tf32(W[(size_t)(k0 + tg + 4) * MD + col]);
            afr[kc][3] = f2tf32(W[(size_t)(k0 + tg + 4) * MD + col + 8]);
        }
    }
    __syncthreads();

    // Ballot compaction helper (t < NN only; warps 0-3 fully active).
    auto compact = [&](int tile, int buf) {
        const float a = __ldg(&adj[(size_t)tile * NN + t]);
        adjA[buf * NN + t] = a;
        const u32 mask = __ballot_sync(0xFFFFFFFFu, a != 0.f);
        int base = 0;
        if (lane == 0 && mask) base = atomicAdd(&nact[buf], (int)__popc(mask));
        base = __shfl_sync(0xFFFFFFFFu, base, 0);
        if (a != 0.f) {
            const int s = base + (int)__popc(mask & ((1u << lane) - 1u));
            if (s < SLOTS) actj[buf * SLOTS + s] = t;
        }
    };

    // Prologue: compact + prefetch the first tile into buffer 0.
    int cur = blockIdx.x;
    if (cur < BB * NN) {
        if (t < NN) compact(cur, 0);
        __syncthreads();
        const int na0 = min(nact[0], SLOTS);
        for (int f = t; f < na0 * 16; f += 256) {
            const int s = f >> 4, j = actj[s];
            cp16(smb + E_OFF + (u32)(s * SJ + (f & 15) * 4) * 4,
                 e + ((size_t)cur * NN + j) * ED + (f & 15) * 4);
        }
    }
    CP_COMMIT();

    int cbuf = 0;
    for (; cur < BB * NN; cur += gridDim.x) {
        const int nb = 1 - cbuf;
        const int nxt = cur + gridDim.x;

        // Compaction for NEXT tile (buffer nb).
        if (nxt < BB * NN && t < NN) compact(nxt, nb);

        // Zero-fill inactive rows of CUR (overlaps with compaction latency).
        float* __restrict__ orow = out + (size_t)cur * NN * MD;
        {
            const float4 z = make_float4(0.f, 0.f, 0.f, 0.f);
#pragma unroll
            for (int i2 = 0; i2 < 16; i2++) {
                const int idx = t + i2 * 256;
                const int j = idx >> 5, q = idx & 31;
                if (adjA[cbuf * NN + j] == 0.f)
                    __stcs(reinterpret_cast<float4*>(&orow[(size_t)j * MD + q * 4]), z);
            }
        }
        __syncthreads();  // compaction of nxt visible

        // Issue cp.asyncs for NEXT tile's active rows.
        if (nxt < BB * NN) {
            const int na2 = min(nact[nb], SLOTS);
            for (int f = t; f < na2 * 16; f += 256) {
                const int s = f >> 4, j = actj[nb * SLOTS + s];
                cp16(smb + E_OFF + (u32)(nb * EBUF + s * SJ + (f & 15) * 4) * 4,
                     e + ((size_t)nxt * NN + j) * ED + (f & 15) * 4);
            }
        }
        CP_COMMIT();
        CP_WAIT1();       // CUR's e data landed (NEXT's group still in flight)
        __syncthreads();  // visible block-wide

        const int na = min(nact[cbuf], SLOTS);
        const float4 c2r = __ldg(reinterpret_cast<const float4*>(
            &g_c2[(size_t)cur * MD + 4 * lane]));
        const float* __restrict__ c1b = g_c1 + (size_t)(cur >> 7) * NN * MD;
        const u32* __restrict__ ebase = e_su + cbuf * EBUF;
        const int nbatch = (na + 31) >> 5;

        for (int sb = 0; sb < nbatch; sb++) {
            float* buf = stg + (sb & 1) * STGF;
            // Ragged batch: only the q-chunks that contain live slots.
            const int qmax = min(4, (na - sb * 32 + 7) >> 3);
            for (int q = 0; q < qmax; q++) {
                const int sl = sb * 32 + q * 8 + g;
                float a0[4] = {0.f, 0.f, 0.f, 0.f};
                const u32* br = &ebase[sl * SJ + tg];
#pragma unroll
                for (int kc = 0; kc < 8; kc++)
                    mma_tf32(a0, afr[kc], br[kc * 8], br[kc * 8 + 4]);
                const int r0 = (q * 8 + 2 * tg) * SM2 + mw + g;
                buf[r0] = a0[0];
                buf[r0 + SM2] = a0[1];
                buf[r0 + 8] = a0[2];
                buf[r0 + SM2 + 8] = a0[3];
            }
            if (sb > 0) {
                const int pb = sb - 1;
                const float* pbuf = stg + (pb & 1) * STGF;
#pragma unroll
                for (int i2 = 0; i2 < 4; i2++) {
                    const int r = i2 * 8 + warp;
                    const int slot = pb * 32 + r;
                    if (slot < na) {
                        const int j = actj[cbuf * SLOTS + slot];
                        const float4 d = *reinterpret_cast<const float4*>(
                            &pbuf[r * SM2 + 4 * lane]);
                        const float4 c1 = __ldg(reinterpret_cast<const float4*>(
                            &c1b[(size_t)j * MD + 4 * lane]));
                        __stcs(reinterpret_cast<float4*>(&orow[(size_t)j * MD + 4 * lane]),
                               make_float4(d.x + c1.x + c2r.x, d.y + c1.y + c2r.y,
                                           d.z + c1.z + c2r.z, d.w + c1.w + c2r.w));
                    }
                }
            }
            __syncthreads();
        }
        if (nbatch > 0) {
            const int pb = nbatch - 1;
            const float* pbuf = stg + (pb & 1) * STGF;
#pragma unroll
            for (int i2 = 0; i2 < 4; i2++) {
                const int r = i2 * 8 + warp;
                const int slot = pb * 32 + r;
                if (slot < na) {
                    const int j = actj[cbuf * SLOTS + slot];
                    const float4 d = *reinterpret_cast<const float4*>(
                        &pbuf[r * SM2 + 4 * lane]);
                    const float4 c1 = __ldg(reinterpret_cast<const float4*>(
                        &c1b[(size_t)j * MD + 4 * lane]));
                    __stcs(reinterpret_cast<float4*>(&orow[(size_t)j * MD + 4 * lane]),
                           make_float4(d.x + c1.x + c2r.x, d.y + c1.y + c2r.y,
                                       d.z + c1.z + c2r.z, d.w + c1.w + c2r.w));
                }
            }
        }
        if (t == 0) nact[cbuf] = 0;
        cbuf = nb;
        __syncthreads();  // epi/actj reuse + nact reset ordered before next compaction
    }
}

extern "C" void kernel_launch(void* const* d_in, const int* in_sizes, int n_in,
                              void* d_out, int out_size) {
    const float* h    = (const float*)d_in[0];
    const float* e    = (const float*)d_in[1];
    const float* adj  = (const float*)d_in[2];
    const float* W    = (const float*)d_in[3];
    const float* bias = (const float*)d_in[4];
    float* out = (float*)d_out;

    cudaFuncSetAttribute(message_kernel,
                         cudaFuncAttributeMaxDynamicSharedMemorySize, SMEM_BYTES);

    precompute_kernel<<<512, 128>>>(h, W, bias);
    message_kernel<<<444, 256, SMEM_BYTES>>>(e, adj, W, out);
}